// round 6
// baseline (speedup 1.0000x reference)
#include <cuda_runtime.h>
#include <cstdint>

#define NN  50000
#define NE  800000
#define DD  64
#define HID 64

// Scratch: aggregation buffer (allocation-free rule -> __device__ global)
__device__ float g_agg[NN * DD];

__device__ __forceinline__ float silu_f(float v) {
    return v * (1.0f / (1.0f + __expf(-v)));
}

// ---------------------------------------------------------------------------
// zero the aggregation scratch (must run every replay)
// ---------------------------------------------------------------------------
__global__ void zero_agg_kernel() {
    int i = blockIdx.x * blockDim.x + threadIdx.x;
    ((float4*)g_agg)[i] = make_float4(0.f, 0.f, 0.f, 0.f);
}

// ---------------------------------------------------------------------------
// Edge kernel: mij = silu(silu([h[row],h[col]]@W1+b1)@W2+b2); agg[row] += mij
// 64 edges per block, 256 threads, register-blocked 4x4 GEMM tiles.
// ---------------------------------------------------------------------------
#define EDGE_SMEM ((64*128 + 128*64 + 64*68) * 4 + 2 * 64 * 4)

__global__ void __launch_bounds__(256, 2) edge_kernel(
    const float* __restrict__ h, const int* __restrict__ erow, const int* __restrict__ ecol,
    const float* __restrict__ W1, const float* __restrict__ b1,
    const float* __restrict__ W2, const float* __restrict__ b2,
    float* __restrict__ mij)
{
    extern __shared__ float sm[];
    float* Xs = sm;                     // 64 x 128
    float* Ws = Xs + 64 * 128;          // 128 x 64 (W1, then W2)
    float* Hs = Ws + 128 * 64;          // 64 x 68 (padded)
    int*   irs = (int*)(Hs + 64 * 68);  // 64 row ids
    int*   ics = irs + 64;              // 64 col ids

    const int tid = threadIdx.x;
    const int eb  = blockIdx.x * 64;

    if (tid < 64)       irs[tid]      = erow[eb + tid];
    else if (tid < 128) ics[tid - 64] = ecol[eb + tid - 64];
    __syncthreads();

    // gather X = [h[row] | h[col]] as float4 (coalesced over 64B chunks)
    const float4* h4 = (const float4*)h;
    float4* X4 = (float4*)Xs;
#pragma unroll
    for (int i = 0; i < 8; i++) {
        int f = i * 256 + tid;
        int r = f >> 5, p = f & 31;
        int node = (p < 16) ? irs[r] : ics[r];
        X4[f] = h4[node * 16 + (p & 15)];
    }
    // stage W1
    float4* Ws4 = (float4*)Ws;
    const float4* W14 = (const float4*)W1;
#pragma unroll
    for (int i = 0; i < 8; i++) Ws4[i * 256 + tid] = W14[i * 256 + tid];
    __syncthreads();

    const int tx = tid & 15, ty = tid >> 4;
    const int r0 = ty * 4, c0 = tx * 4;

    float acc[4][4];
#pragma unroll
    for (int i = 0; i < 4; i++)
#pragma unroll
        for (int j = 0; j < 4; j++) acc[i][j] = 0.f;

    // layer 1: [64x128] @ [128x64]
#pragma unroll 4
    for (int k = 0; k < 128; k++) {
        float4 w = *(const float4*)&Ws[k * 64 + c0];
#pragma unroll
        for (int i = 0; i < 4; i++) {
            float x = Xs[(r0 + i) * 128 + k];
            acc[i][0] += x * w.x; acc[i][1] += x * w.y;
            acc[i][2] += x * w.z; acc[i][3] += x * w.w;
        }
    }
    {
        float4 bb = *(const float4*)&b1[c0];
#pragma unroll
        for (int i = 0; i < 4; i++) {
            float4 v;
            v.x = silu_f(acc[i][0] + bb.x);
            v.y = silu_f(acc[i][1] + bb.y);
            v.z = silu_f(acc[i][2] + bb.z);
            v.w = silu_f(acc[i][3] + bb.w);
            *(float4*)&Hs[(r0 + i) * 68 + c0] = v;
        }
    }
    __syncthreads();
    // stage W2
    const float4* W24 = (const float4*)W2;
#pragma unroll
    for (int i = 0; i < 4; i++) Ws4[i * 256 + tid] = W24[i * 256 + tid];
    __syncthreads();

#pragma unroll
    for (int i = 0; i < 4; i++)
#pragma unroll
        for (int j = 0; j < 4; j++) acc[i][j] = 0.f;

    // layer 2: [64x64] @ [64x64]
#pragma unroll 4
    for (int k = 0; k < 64; k++) {
        float4 w = *(const float4*)&Ws[k * 64 + c0];
#pragma unroll
        for (int i = 0; i < 4; i++) {
            float x = Hs[(r0 + i) * 68 + k];
            acc[i][0] += x * w.x; acc[i][1] += x * w.y;
            acc[i][2] += x * w.z; acc[i][3] += x * w.w;
        }
    }
    float4 b2v = *(const float4*)&b2[c0];
#pragma unroll
    for (int i = 0; i < 4; i++) {
        float4 m;
        m.x = silu_f(acc[i][0] + b2v.x);
        m.y = silu_f(acc[i][1] + b2v.y);
        m.z = silu_f(acc[i][2] + b2v.z);
        m.w = silu_f(acc[i][3] + b2v.w);
        size_t ge = (size_t)(eb + r0 + i);
        *(float4*)&mij[ge * 64 + c0] = m;
        float* ap = &g_agg[(size_t)irs[r0 + i] * 64 + c0];
        asm volatile("red.global.add.v4.f32 [%0], {%1,%2,%3,%4};"
                     :: "l"(ap), "f"(m.x), "f"(m.y), "f"(m.z), "f"(m.w) : "memory");
    }
}

// ---------------------------------------------------------------------------
// 3-qubit statevector circuit (per node, per thread)
// idx = b0*4 + b1*2 + b2 ; Z eigenvalue: bit 0 -> +1, bit 1 -> -1
// ---------------------------------------------------------------------------
__device__ __forceinline__ void apply_rx3(float* ar, float* ai, float cb, float sb) {
#pragma unroll
    for (int q = 0; q < 3; q++) {
        int st = 4 >> q;
#pragma unroll
        for (int i = 0; i < 8; i++) {
            if (i & st) continue;
            int j = i + st;
            float a0r = ar[i], a0i = ai[i], a1r = ar[j], a1i = ai[j];
            ar[i] =  cb * a0r + sb * a1i;
            ai[i] =  cb * a0i - sb * a1r;
            ar[j] =  sb * a0i + cb * a1r;
            ai[j] = -sb * a0r + cb * a1i;
        }
    }
}

__device__ __forceinline__ void apply_rz(float* ar, float* ai, int st, float theta) {
    float s, c;
    sincosf(0.5f * theta, &s, &c);
#pragma unroll
    for (int i = 0; i < 8; i++) {
        float r = ar[i], im = ai[i];
        if (i & st) { ar[i] = r * c - im * s; ai[i] = im * c + r * s; }
        else        { ar[i] = r * c + im * s; ai[i] = im * c - r * s; }
    }
}

__device__ __forceinline__ void apply_h(float* ar, float* ai, int st) {
    const float SQ = 0.70710678118654752f;
#pragma unroll
    for (int i = 0; i < 8; i++) {
        if (i & st) continue;
        int j = i + st;
        float a0r = ar[i], a0i = ai[i], a1r = ar[j], a1i = ai[j];
        ar[i] = (a0r + a1r) * SQ; ai[i] = (a0i + a1i) * SQ;
        ar[j] = (a0r - a1r) * SQ; ai[j] = (a0i - a1i) * SQ;
    }
}

__device__ void qcircuit(const float* x, float alpha, float beta, float gamma, float delta,
                         const float* __restrict__ Lam, float* outq)
{
    float ar[8], ai[8];
#pragma unroll
    for (int i = 0; i < 8; i++) { ar[i] = 0.f; ai[i] = 0.f; }
    ar[0] = 1.f;

    // 1) data-encoding RY(alpha * x_q)
#pragma unroll
    for (int q = 0; q < 3; q++) {
        float s, c;
        sincosf(0.5f * alpha * x[q], &s, &c);
        int st = 4 >> q;
#pragma unroll
        for (int i = 0; i < 8; i++) {
            if (i & st) continue;
            int j = i + st;
            float a0r = ar[i], a0i = ai[i], a1r = ar[j], a1i = ai[j];
            ar[i] = c * a0r - s * a1r; ai[i] = c * a0i - s * a1i;
            ar[j] = s * a0r + c * a1r; ai[j] = s * a0i + c * a1i;
        }
    }
    // 2) IsingZZ coupling: amp *= exp(-0.5i * phi * z_i * z_j)
#pragma unroll
    for (int qi = 0; qi < 3; qi++)
#pragma unroll
        for (int qj = qi + 1; qj < 3; qj++) {
            float phi = 0.5f * gamma * (Lam[qi * 3 + qj] + Lam[qj * 3 + qi]);
            float sp, cp;
            sincosf(0.5f * phi, &sp, &cp);
#pragma unroll
            for (int i = 0; i < 8; i++) {
                int bi = (i >> (2 - qi)) & 1, bj = (i >> (2 - qj)) & 1;
                float pi = (bi ^ bj) ? sp : -sp;   // equal bits: z_i z_j=+1 -> e^{-i phi/2}
                float r = ar[i] * cp - ai[i] * pi;
                ai[i]   = ar[i] * pi + ai[i] * cp;
                ar[i]   = r;
            }
        }
    // 3) kinetic RX(beta)
    float sb, cb;
    sincosf(0.5f * beta, &sb, &cb);
    apply_rx3(ar, ai, cb, sb);
    // 4) anharmonic: RZ(delta*(1-0.5x^2)), H, RZ(delta*x^2), H per qubit
#pragma unroll
    for (int q = 0; q < 3; q++) {
        int st = 4 >> q;
        float x2 = x[q] * x[q];
        apply_rz(ar, ai, st, delta * (1.f - 0.5f * x2));
        apply_h(ar, ai, st);
        apply_rz(ar, ai, st, delta * x2);
        apply_h(ar, ai, st);
    }
    // 5) final RX(beta)
    apply_rx3(ar, ai, cb, sb);

    float e0 = 0.f, e1 = 0.f, e2 = 0.f;
#pragma unroll
    for (int i = 0; i < 8; i++) {
        float p = ar[i] * ar[i] + ai[i] * ai[i];
        e0 += (i & 4) ? -p : p;
        e1 += (i & 2) ? -p : p;
        e2 += (i & 1) ? -p : p;
    }
    outq[0] = e0; outq[1] = e1; outq[2] = e2;
}

// ---------------------------------------------------------------------------
// Node kernel: a=[h,agg/100]; q_in = silu(a@qW1+qb1)@qW2+qb2; q_out = circuit;
// out = h + silu([a,q_out]@pW1+pb1)@pW2+pb2.  64 nodes per block.
// ---------------------------------------------------------------------------
#define NODE_SMEM ((64*132 + 131*64 + 64*68) * 4)

__global__ void __launch_bounds__(256, 2) node_kernel(
    const float* __restrict__ h,
    const float* __restrict__ qW1, const float* __restrict__ qb1,
    const float* __restrict__ qW2, const float* __restrict__ qb2,
    const float* __restrict__ pW1, const float* __restrict__ pb1,
    const float* __restrict__ pW2, const float* __restrict__ pb2,
    const float* __restrict__ alpha_p, const float* __restrict__ beta_p,
    const float* __restrict__ gamma_p, const float* __restrict__ delta_p,
    const float* __restrict__ Lam,
    float* __restrict__ out)
{
    extern __shared__ float sm[];
    float* Xs = sm;              // 64 x 132 : [h(64) | agg/100(64) | q_out(3) | pad]
    float* Ws = Xs + 64 * 132;   // up to 131 x 64
    float* Hs = Ws + 131 * 64;   // 64 x 68

    const int tid = threadIdx.x;
    const int nb  = blockIdx.x * 64;

    const float4* h4 = (const float4*)h;
    const float4* a4 = (const float4*)g_agg;
#pragma unroll
    for (int i = 0; i < 8; i++) {
        int f = i * 256 + tid;
        int r = f >> 5, p = f & 31;
        int node = nb + r;
        float4 v = make_float4(0.f, 0.f, 0.f, 0.f);
        if (node < NN) {
            if (p < 16) v = h4[node * 16 + p];
            else {
                v = a4[node * 16 + (p - 16)];
                v.x *= 0.01f; v.y *= 0.01f; v.z *= 0.01f; v.w *= 0.01f;
            }
        }
        ((float4*)Xs)[r * 33 + p] = v;
    }
    if (tid < 64) ((float4*)Xs)[tid * 33 + 32] = make_float4(0.f, 0.f, 0.f, 0.f);

    float4* Ws4 = (float4*)Ws;
#pragma unroll
    for (int i = 0; i < 8; i++) Ws4[i * 256 + tid] = ((const float4*)qW1)[i * 256 + tid];
    __syncthreads();

    const int tx = tid & 15, ty = tid >> 4;
    const int r0 = ty * 4, c0 = tx * 4;
    float acc[4][4];

    // phase A: H = silu(X[:, :128] @ qW1 + qb1)
#pragma unroll
    for (int i = 0; i < 4; i++)
#pragma unroll
        for (int j = 0; j < 4; j++) acc[i][j] = 0.f;
#pragma unroll 4
    for (int k = 0; k < 128; k++) {
        float4 w = *(const float4*)&Ws[k * 64 + c0];
#pragma unroll
        for (int i = 0; i < 4; i++) {
            float x = Xs[(r0 + i) * 132 + k];
            acc[i][0] += x * w.x; acc[i][1] += x * w.y;
            acc[i][2] += x * w.z; acc[i][3] += x * w.w;
        }
    }
    {
        float4 bb = *(const float4*)&qb1[c0];
#pragma unroll
        for (int i = 0; i < 4; i++) {
            float4 v;
            v.x = silu_f(acc[i][0] + bb.x);
            v.y = silu_f(acc[i][1] + bb.y);
            v.z = silu_f(acc[i][2] + bb.z);
            v.w = silu_f(acc[i][3] + bb.w);
            *(float4*)&Hs[(r0 + i) * 68 + c0] = v;
        }
    }
    __syncthreads();

    // phase B: q_in = H @ qW2 + qb2 ; quantum circuit (one thread per node)
    if (tid < 64) {
        float qin[3] = { qb2[0], qb2[1], qb2[2] };
        for (int k = 0; k < 64; k++) {
            float hv = Hs[tid * 68 + k];
            qin[0] += hv * qW2[k * 3 + 0];
            qin[1] += hv * qW2[k * 3 + 1];
            qin[2] += hv * qW2[k * 3 + 2];
        }
        float qo[3];
        qcircuit(qin, *alpha_p, *beta_p, *gamma_p, *delta_p, Lam, qo);
        Xs[tid * 132 + 128] = qo[0];
        Xs[tid * 132 + 129] = qo[1];
        Xs[tid * 132 + 130] = qo[2];
    }
    __syncthreads();

    // stage pW1 (131x64)
    for (int f = tid; f < 2096; f += 256) Ws4[f] = ((const float4*)pW1)[f];
    __syncthreads();

    // phase C: P = silu(X[:, :131] @ pW1 + pb1)
#pragma unroll
    for (int i = 0; i < 4; i++)
#pragma unroll
        for (int j = 0; j < 4; j++) acc[i][j] = 0.f;
    for (int k = 0; k < 131; k++) {
        float4 w = *(const float4*)&Ws[k * 64 + c0];
#pragma unroll
        for (int i = 0; i < 4; i++) {
            float x = Xs[(r0 + i) * 132 + k];
            acc[i][0] += x * w.x; acc[i][1] += x * w.y;
            acc[i][2] += x * w.z; acc[i][3] += x * w.w;
        }
    }
    {
        float4 bb = *(const float4*)&pb1[c0];
#pragma unroll
        for (int i = 0; i < 4; i++) {
            float4 v;
            v.x = silu_f(acc[i][0] + bb.x);
            v.y = silu_f(acc[i][1] + bb.y);
            v.z = silu_f(acc[i][2] + bb.z);
            v.w = silu_f(acc[i][3] + bb.w);
            *(float4*)&Hs[(r0 + i) * 68 + c0] = v;
        }
    }
    __syncthreads();

    // stage pW2 (64x64)
    for (int f = tid; f < 1024; f += 256) Ws4[f] = ((const float4*)pW2)[f];
    __syncthreads();

    // phase D: out = h + P @ pW2 + pb2
#pragma unroll
    for (int i = 0; i < 4; i++)
#pragma unroll
        for (int j = 0; j < 4; j++) acc[i][j] = 0.f;
#pragma unroll 4
    for (int k = 0; k < 64; k++) {
        float4 w = *(const float4*)&Ws[k * 64 + c0];
#pragma unroll
        for (int i = 0; i < 4; i++) {
            float x = Hs[(r0 + i) * 68 + k];
            acc[i][0] += x * w.x; acc[i][1] += x * w.y;
            acc[i][2] += x * w.z; acc[i][3] += x * w.w;
        }
    }
    float4 bb = *(const float4*)&pb2[c0];
#pragma unroll
    for (int i = 0; i < 4; i++) {
        int node = nb + r0 + i;
        if (node < NN) {
            float4 v;
            v.x = Xs[(r0 + i) * 132 + c0 + 0] + acc[i][0] + bb.x;
            v.y = Xs[(r0 + i) * 132 + c0 + 1] + acc[i][1] + bb.y;
            v.z = Xs[(r0 + i) * 132 + c0 + 2] + acc[i][2] + bb.z;
            v.w = Xs[(r0 + i) * 132 + c0 + 3] + acc[i][3] + bb.w;
            *(float4*)&out[(size_t)node * 64 + c0] = v;
        }
    }
}

// ---------------------------------------------------------------------------
extern "C" void kernel_launch(void* const* d_in, const int* in_sizes, int n_in,
                              void* d_out, int out_size) {
    const float* h   = (const float*)d_in[0];
    const int*   ei  = (const int*)d_in[1];
    const float* eW1 = (const float*)d_in[2];
    const float* eb1 = (const float*)d_in[3];
    const float* eW2 = (const float*)d_in[4];
    const float* eb2 = (const float*)d_in[5];
    const float* qW1 = (const float*)d_in[6];
    const float* qb1 = (const float*)d_in[7];
    const float* qW2 = (const float*)d_in[8];
    const float* qb2 = (const float*)d_in[9];
    const float* pW1 = (const float*)d_in[10];
    const float* pb1 = (const float*)d_in[11];
    const float* pW2 = (const float*)d_in[12];
    const float* pb2 = (const float*)d_in[13];
    const float* al  = (const float*)d_in[14];
    const float* be  = (const float*)d_in[15];
    const float* ga  = (const float*)d_in[16];
    const float* de  = (const float*)d_in[17];
    const float* Lam = (const float*)d_in[18];

    float* out = (float*)d_out;
    // Outputs are (out [NN*DD], mij [NE*DD]) concatenated.
    float* mij = out + (size_t)NN * DD;

    cudaFuncSetAttribute(edge_kernel, cudaFuncAttributeMaxDynamicSharedMemorySize, EDGE_SMEM);
    cudaFuncSetAttribute(node_kernel, cudaFuncAttributeMaxDynamicSharedMemorySize, NODE_SMEM);

    zero_agg_kernel<<<(NN * DD / 4) / 256, 256>>>();
    edge_kernel<<<NE / 64, 256, EDGE_SMEM>>>(h, ei, ei + NE, eW1, eb1, eW2, eb2, mij);
    node_kernel<<<(NN + 63) / 64, 256, NODE_SMEM>>>(h, qW1, qb1, qW2, qb2,
                                                    pW1, pb1, pW2, pb2,
                                                    al, be, ga, de, Lam, out);
}

// round 7
// speedup vs baseline: 1.0019x; 1.0019x over previous
#include <cuda_runtime.h>
#include <cstdint>

#define NN  50000
#define NE  800000
#define DD  64
#define HID 64

// Scratch: aggregation buffer (allocation-free rule -> __device__ global)
__device__ float g_agg[NN * DD];

__device__ __forceinline__ float silu_f(float v) {
    return v * (1.0f / (1.0f + __expf(-v)));
}

// ---------------------------------------------------------------------------
// zero the aggregation scratch (must run every replay)
// ---------------------------------------------------------------------------
__global__ void zero_agg_kernel() {
    int i = blockIdx.x * blockDim.x + threadIdx.x;
    ((float4*)g_agg)[i] = make_float4(0.f, 0.f, 0.f, 0.f);
}

// ---------------------------------------------------------------------------
// Edge kernel: mij = silu(silu([h[row],h[col]]@W1+b1)@W2+b2); agg[row] += mij
// 64 edges per block, 256 threads, register-blocked 4x4 GEMM tiles.
// ---------------------------------------------------------------------------
#define EDGE_SMEM ((64*128 + 128*64 + 64*68) * 4 + 2 * 64 * 4)

__global__ void __launch_bounds__(256, 2) edge_kernel(
    const float* __restrict__ h, const int* __restrict__ erow, const int* __restrict__ ecol,
    const float* __restrict__ W1, const float* __restrict__ b1,
    const float* __restrict__ W2, const float* __restrict__ b2,
    float* __restrict__ mij)
{
    extern __shared__ float sm[];
    float* Xs = sm;                     // 64 x 128
    float* Ws = Xs + 64 * 128;          // 128 x 64 (W1, then W2)
    float* Hs = Ws + 128 * 64;          // 64 x 68 (padded)
    int*   irs = (int*)(Hs + 64 * 68);  // 64 row ids
    int*   ics = irs + 64;              // 64 col ids

    const int tid = threadIdx.x;
    const int eb  = blockIdx.x * 64;

    if (tid < 64)       irs[tid]      = erow[eb + tid];
    else if (tid < 128) ics[tid - 64] = ecol[eb + tid - 64];
    __syncthreads();

    // gather X = [h[row] | h[col]] as float4 (coalesced over 64B chunks)
    const float4* h4 = (const float4*)h;
    float4* X4 = (float4*)Xs;
#pragma unroll
    for (int i = 0; i < 8; i++) {
        int f = i * 256 + tid;
        int r = f >> 5, p = f & 31;
        int node = (p < 16) ? irs[r] : ics[r];
        X4[f] = h4[node * 16 + (p & 15)];
    }
    // stage W1
    float4* Ws4 = (float4*)Ws;
    const float4* W14 = (const float4*)W1;
#pragma unroll
    for (int i = 0; i < 8; i++) Ws4[i * 256 + tid] = W14[i * 256 + tid];
    __syncthreads();

    const int tx = tid & 15, ty = tid >> 4;
    const int r0 = ty * 4, c0 = tx * 4;

    float acc[4][4];
#pragma unroll
    for (int i = 0; i < 4; i++)
#pragma unroll
        for (int j = 0; j < 4; j++) acc[i][j] = 0.f;

    // layer 1: [64x128] @ [128x64]
#pragma unroll 4
    for (int k = 0; k < 128; k++) {
        float4 w = *(const float4*)&Ws[k * 64 + c0];
#pragma unroll
        for (int i = 0; i < 4; i++) {
            float x = Xs[(r0 + i) * 128 + k];
            acc[i][0] += x * w.x; acc[i][1] += x * w.y;
            acc[i][2] += x * w.z; acc[i][3] += x * w.w;
        }
    }
    {
        float4 bb = *(const float4*)&b1[c0];
#pragma unroll
        for (int i = 0; i < 4; i++) {
            float4 v;
            v.x = silu_f(acc[i][0] + bb.x);
            v.y = silu_f(acc[i][1] + bb.y);
            v.z = silu_f(acc[i][2] + bb.z);
            v.w = silu_f(acc[i][3] + bb.w);
            *(float4*)&Hs[(r0 + i) * 68 + c0] = v;
        }
    }
    __syncthreads();
    // stage W2
    const float4* W24 = (const float4*)W2;
#pragma unroll
    for (int i = 0; i < 4; i++) Ws4[i * 256 + tid] = W24[i * 256 + tid];
    __syncthreads();

#pragma unroll
    for (int i = 0; i < 4; i++)
#pragma unroll
        for (int j = 0; j < 4; j++) acc[i][j] = 0.f;

    // layer 2: [64x64] @ [64x64]
#pragma unroll 4
    for (int k = 0; k < 64; k++) {
        float4 w = *(const float4*)&Ws[k * 64 + c0];
#pragma unroll
        for (int i = 0; i < 4; i++) {
            float x = Hs[(r0 + i) * 68 + k];
            acc[i][0] += x * w.x; acc[i][1] += x * w.y;
            acc[i][2] += x * w.z; acc[i][3] += x * w.w;
        }
    }
    float4 b2v = *(const float4*)&b2[c0];
#pragma unroll
    for (int i = 0; i < 4; i++) {
        float4 m;
        m.x = silu_f(acc[i][0] + b2v.x);
        m.y = silu_f(acc[i][1] + b2v.y);
        m.z = silu_f(acc[i][2] + b2v.z);
        m.w = silu_f(acc[i][3] + b2v.w);
        size_t ge = (size_t)(eb + r0 + i);
        *(float4*)&mij[ge * 64 + c0] = m;
        float* ap = &g_agg[(size_t)irs[r0 + i] * 64 + c0];
        asm volatile("red.global.add.v4.f32 [%0], {%1,%2,%3,%4};"
                     :: "l"(ap), "f"(m.x), "f"(m.y), "f"(m.z), "f"(m.w) : "memory");
    }
}

// ---------------------------------------------------------------------------
// 3-qubit statevector circuit (per node, per thread)
// idx = b0*4 + b1*2 + b2 ; Z eigenvalue: bit 0 -> +1, bit 1 -> -1
// ---------------------------------------------------------------------------
__device__ __forceinline__ void apply_rx3(float* ar, float* ai, float cb, float sb) {
#pragma unroll
    for (int q = 0; q < 3; q++) {
        int st = 4 >> q;
#pragma unroll
        for (int i = 0; i < 8; i++) {
            if (i & st) continue;
            int j = i + st;
            float a0r = ar[i], a0i = ai[i], a1r = ar[j], a1i = ai[j];
            ar[i] =  cb * a0r + sb * a1i;
            ai[i] =  cb * a0i - sb * a1r;
            ar[j] =  sb * a0i + cb * a1r;
            ai[j] = -sb * a0r + cb * a1i;
        }
    }
}

__device__ __forceinline__ void apply_rz(float* ar, float* ai, int st, float theta) {
    float s, c;
    sincosf(0.5f * theta, &s, &c);
#pragma unroll
    for (int i = 0; i < 8; i++) {
        float r = ar[i], im = ai[i];
        if (i & st) { ar[i] = r * c - im * s; ai[i] = im * c + r * s; }
        else        { ar[i] = r * c + im * s; ai[i] = im * c - r * s; }
    }
}

__device__ __forceinline__ void apply_h(float* ar, float* ai, int st) {
    const float SQ = 0.70710678118654752f;
#pragma unroll
    for (int i = 0; i < 8; i++) {
        if (i & st) continue;
        int j = i + st;
        float a0r = ar[i], a0i = ai[i], a1r = ar[j], a1i = ai[j];
        ar[i] = (a0r + a1r) * SQ; ai[i] = (a0i + a1i) * SQ;
        ar[j] = (a0r - a1r) * SQ; ai[j] = (a0i - a1i) * SQ;
    }
}

__device__ void qcircuit(const float* x, float alpha, float beta, float gamma, float delta,
                         const float* __restrict__ Lam, float* outq)
{
    float ar[8], ai[8];
#pragma unroll
    for (int i = 0; i < 8; i++) { ar[i] = 0.f; ai[i] = 0.f; }
    ar[0] = 1.f;

    // 1) data-encoding RY(alpha * x_q)
#pragma unroll
    for (int q = 0; q < 3; q++) {
        float s, c;
        sincosf(0.5f * alpha * x[q], &s, &c);
        int st = 4 >> q;
#pragma unroll
        for (int i = 0; i < 8; i++) {
            if (i & st) continue;
            int j = i + st;
            float a0r = ar[i], a0i = ai[i], a1r = ar[j], a1i = ai[j];
            ar[i] = c * a0r - s * a1r; ai[i] = c * a0i - s * a1i;
            ar[j] = s * a0r + c * a1r; ai[j] = s * a0i + c * a1i;
        }
    }
    // 2) IsingZZ coupling: amp *= exp(-0.5i * phi * z_i * z_j)
#pragma unroll
    for (int qi = 0; qi < 3; qi++)
#pragma unroll
        for (int qj = qi + 1; qj < 3; qj++) {
            float phi = 0.5f * gamma * (Lam[qi * 3 + qj] + Lam[qj * 3 + qi]);
            float sp, cp;
            sincosf(0.5f * phi, &sp, &cp);
#pragma unroll
            for (int i = 0; i < 8; i++) {
                int bi = (i >> (2 - qi)) & 1, bj = (i >> (2 - qj)) & 1;
                float pi = (bi ^ bj) ? sp : -sp;   // equal bits: z_i z_j=+1 -> e^{-i phi/2}
                float r = ar[i] * cp - ai[i] * pi;
                ai[i]   = ar[i] * pi + ai[i] * cp;
                ar[i]   = r;
            }
        }
    // 3) kinetic RX(beta)
    float sb, cb;
    sincosf(0.5f * beta, &sb, &cb);
    apply_rx3(ar, ai, cb, sb);
    // 4) anharmonic: RZ(delta*(1-0.5x^2)), H, RZ(delta*x^2), H per qubit
#pragma unroll
    for (int q = 0; q < 3; q++) {
        int st = 4 >> q;
        float x2 = x[q] * x[q];
        apply_rz(ar, ai, st, delta * (1.f - 0.5f * x2));
        apply_h(ar, ai, st);
        apply_rz(ar, ai, st, delta * x2);
        apply_h(ar, ai, st);
    }
    // 5) final RX(beta)
    apply_rx3(ar, ai, cb, sb);

    float e0 = 0.f, e1 = 0.f, e2 = 0.f;
#pragma unroll
    for (int i = 0; i < 8; i++) {
        float p = ar[i] * ar[i] + ai[i] * ai[i];
        e0 += (i & 4) ? -p : p;
        e1 += (i & 2) ? -p : p;
        e2 += (i & 1) ? -p : p;
    }
    outq[0] = e0; outq[1] = e1; outq[2] = e2;
}

// ---------------------------------------------------------------------------
// Node kernel: a=[h,agg/100]; q_in = silu(a@qW1+qb1)@qW2+qb2; q_out = circuit;
// out = h + silu([a,q_out]@pW1+pb1)@pW2+pb2.  64 nodes per block.
// ---------------------------------------------------------------------------
#define NODE_SMEM ((64*132 + 131*64 + 64*68) * 4)

__global__ void __launch_bounds__(256, 2) node_kernel(
    const float* __restrict__ h,
    const float* __restrict__ qW1, const float* __restrict__ qb1,
    const float* __restrict__ qW2, const float* __restrict__ qb2,
    const float* __restrict__ pW1, const float* __restrict__ pb1,
    const float* __restrict__ pW2, const float* __restrict__ pb2,
    const float* __restrict__ alpha_p, const float* __restrict__ beta_p,
    const float* __restrict__ gamma_p, const float* __restrict__ delta_p,
    const float* __restrict__ Lam,
    float* __restrict__ out)
{
    extern __shared__ float sm[];
    float* Xs = sm;              // 64 x 132 : [h(64) | agg/100(64) | q_out(3) | pad]
    float* Ws = Xs + 64 * 132;   // up to 131 x 64
    float* Hs = Ws + 131 * 64;   // 64 x 68

    const int tid = threadIdx.x;
    const int nb  = blockIdx.x * 64;

    const float4* h4 = (const float4*)h;
    const float4* a4 = (const float4*)g_agg;
#pragma unroll
    for (int i = 0; i < 8; i++) {
        int f = i * 256 + tid;
        int r = f >> 5, p = f & 31;
        int node = nb + r;
        float4 v = make_float4(0.f, 0.f, 0.f, 0.f);
        if (node < NN) {
            if (p < 16) v = h4[node * 16 + p];
            else {
                v = a4[node * 16 + (p - 16)];
                v.x *= 0.01f; v.y *= 0.01f; v.z *= 0.01f; v.w *= 0.01f;
            }
        }
        ((float4*)Xs)[r * 33 + p] = v;
    }
    if (tid < 64) ((float4*)Xs)[tid * 33 + 32] = make_float4(0.f, 0.f, 0.f, 0.f);

    float4* Ws4 = (float4*)Ws;
#pragma unroll
    for (int i = 0; i < 8; i++) Ws4[i * 256 + tid] = ((const float4*)qW1)[i * 256 + tid];
    __syncthreads();

    const int tx = tid & 15, ty = tid >> 4;
    const int r0 = ty * 4, c0 = tx * 4;
    float acc[4][4];

    // phase A: H = silu(X[:, :128] @ qW1 + qb1)
#pragma unroll
    for (int i = 0; i < 4; i++)
#pragma unroll
        for (int j = 0; j < 4; j++) acc[i][j] = 0.f;
#pragma unroll 4
    for (int k = 0; k < 128; k++) {
        float4 w = *(const float4*)&Ws[k * 64 + c0];
#pragma unroll
        for (int i = 0; i < 4; i++) {
            float x = Xs[(r0 + i) * 132 + k];
            acc[i][0] += x * w.x; acc[i][1] += x * w.y;
            acc[i][2] += x * w.z; acc[i][3] += x * w.w;
        }
    }
    {
        float4 bb = *(const float4*)&qb1[c0];
#pragma unroll
        for (int i = 0; i < 4; i++) {
            float4 v;
            v.x = silu_f(acc[i][0] + bb.x);
            v.y = silu_f(acc[i][1] + bb.y);
            v.z = silu_f(acc[i][2] + bb.z);
            v.w = silu_f(acc[i][3] + bb.w);
            *(float4*)&Hs[(r0 + i) * 68 + c0] = v;
        }
    }
    __syncthreads();

    // phase B: q_in = H @ qW2 + qb2 ; quantum circuit (one thread per node)
    if (tid < 64) {
        float qin[3] = { qb2[0], qb2[1], qb2[2] };
        for (int k = 0; k < 64; k++) {
            float hv = Hs[tid * 68 + k];
            qin[0] += hv * qW2[k * 3 + 0];
            qin[1] += hv * qW2[k * 3 + 1];
            qin[2] += hv * qW2[k * 3 + 2];
        }
        float qo[3];
        qcircuit(qin, *alpha_p, *beta_p, *gamma_p, *delta_p, Lam, qo);
        Xs[tid * 132 + 128] = qo[0];
        Xs[tid * 132 + 129] = qo[1];
        Xs[tid * 132 + 130] = qo[2];
    }
    __syncthreads();

    // stage pW1 (131x64)
    for (int f = tid; f < 2096; f += 256) Ws4[f] = ((const float4*)pW1)[f];
    __syncthreads();

    // phase C: P = silu(X[:, :131] @ pW1 + pb1)
#pragma unroll
    for (int i = 0; i < 4; i++)
#pragma unroll
        for (int j = 0; j < 4; j++) acc[i][j] = 0.f;
    for (int k = 0; k < 131; k++) {
        float4 w = *(const float4*)&Ws[k * 64 + c0];
#pragma unroll
        for (int i = 0; i < 4; i++) {
            float x = Xs[(r0 + i) * 132 + k];
            acc[i][0] += x * w.x; acc[i][1] += x * w.y;
            acc[i][2] += x * w.z; acc[i][3] += x * w.w;
        }
    }
    {
        float4 bb = *(const float4*)&pb1[c0];
#pragma unroll
        for (int i = 0; i < 4; i++) {
            float4 v;
            v.x = silu_f(acc[i][0] + bb.x);
            v.y = silu_f(acc[i][1] + bb.y);
            v.z = silu_f(acc[i][2] + bb.z);
            v.w = silu_f(acc[i][3] + bb.w);
            *(float4*)&Hs[(r0 + i) * 68 + c0] = v;
        }
    }
    __syncthreads();

    // stage pW2 (64x64)
    for (int f = tid; f < 1024; f += 256) Ws4[f] = ((const float4*)pW2)[f];
    __syncthreads();

    // phase D: out = h + P @ pW2 + pb2
#pragma unroll
    for (int i = 0; i < 4; i++)
#pragma unroll
        for (int j = 0; j < 4; j++) acc[i][j] = 0.f;
#pragma unroll 4
    for (int k = 0; k < 64; k++) {
        float4 w = *(const float4*)&Ws[k * 64 + c0];
#pragma unroll
        for (int i = 0; i < 4; i++) {
            float x = Hs[(r0 + i) * 68 + k];
            acc[i][0] += x * w.x; acc[i][1] += x * w.y;
            acc[i][2] += x * w.z; acc[i][3] += x * w.w;
        }
    }
    float4 bb = *(const float4*)&pb2[c0];
#pragma unroll
    for (int i = 0; i < 4; i++) {
        int node = nb + r0 + i;
        if (node < NN) {
            float4 v;
            v.x = Xs[(r0 + i) * 132 + c0 + 0] + acc[i][0] + bb.x;
            v.y = Xs[(r0 + i) * 132 + c0 + 1] + acc[i][1] + bb.y;
            v.z = Xs[(r0 + i) * 132 + c0 + 2] + acc[i][2] + bb.z;
            v.w = Xs[(r0 + i) * 132 + c0 + 3] + acc[i][3] + bb.w;
            *(float4*)&out[(size_t)node * 64 + c0] = v;
        }
    }
}

// ---------------------------------------------------------------------------
extern "C" void kernel_launch(void* const* d_in, const int* in_sizes, int n_in,
                              void* d_out, int out_size) {
    const float* h   = (const float*)d_in[0];
    const int*   ei  = (const int*)d_in[1];
    const float* eW1 = (const float*)d_in[2];
    const float* eb1 = (const float*)d_in[3];
    const float* eW2 = (const float*)d_in[4];
    const float* eb2 = (const float*)d_in[5];
    const float* qW1 = (const float*)d_in[6];
    const float* qb1 = (const float*)d_in[7];
    const float* qW2 = (const float*)d_in[8];
    const float* qb2 = (const float*)d_in[9];
    const float* pW1 = (const float*)d_in[10];
    const float* pb1 = (const float*)d_in[11];
    const float* pW2 = (const float*)d_in[12];
    const float* pb2 = (const float*)d_in[13];
    const float* al  = (const float*)d_in[14];
    const float* be  = (const float*)d_in[15];
    const float* ga  = (const float*)d_in[16];
    const float* de  = (const float*)d_in[17];
    const float* Lam = (const float*)d_in[18];

    float* out = (float*)d_out;
    // Outputs are (out [NN*DD], mij [NE*DD]) concatenated.
    float* mij = out + (size_t)NN * DD;

    cudaFuncSetAttribute(edge_kernel, cudaFuncAttributeMaxDynamicSharedMemorySize, EDGE_SMEM);
    cudaFuncSetAttribute(node_kernel, cudaFuncAttributeMaxDynamicSharedMemorySize, NODE_SMEM);

    zero_agg_kernel<<<(NN * DD / 4) / 256, 256>>>();
    edge_kernel<<<NE / 64, 256, EDGE_SMEM>>>(h, ei, ei + NE, eW1, eb1, eW2, eb2, mij);
    node_kernel<<<(NN + 63) / 64, 256, NODE_SMEM>>>(h, qW1, qb1, qW2, qb2,
                                                    pW1, pb1, pW2, pb2,
                                                    al, be, ga, de, Lam, out);
}

// round 8
// speedup vs baseline: 1.2090x; 1.2067x over previous
#include <cuda_runtime.h>
#include <cstdint>

#define NN  50000
#define NE  800000
#define DD  64
#define HID 64

// Scratch: aggregation buffer (allocation-free rule -> __device__ global)
__device__ float g_agg[NN * DD];

__device__ __forceinline__ float silu_f(float v) {
    return v * (1.0f / (1.0f + __expf(-v)));
}

// ---------------- packed f32x2 helpers (Blackwell FFMA2) --------------------
__device__ __forceinline__ uint64_t dupf(float x) {
    uint64_t r; asm("mov.b64 %0, {%1, %1};" : "=l"(r) : "f"(x)); return r;
}
__device__ __forceinline__ uint64_t pk2(float lo, float hi) {
    uint64_t r; asm("mov.b64 %0, {%1, %2};" : "=l"(r) : "f"(lo), "f"(hi)); return r;
}
__device__ __forceinline__ void fma2(uint64_t& d, uint64_t a, uint64_t b) {
    asm("fma.rn.f32x2 %0, %1, %2, %0;" : "+l"(d) : "l"(a), "l"(b));
}
__device__ __forceinline__ float2 unpk(uint64_t v) {
    float2 f; asm("mov.b64 {%0, %1}, %2;" : "=f"(f.x), "=f"(f.y) : "l"(v)); return f;
}

// ---------------------------------------------------------------------------
// zero the aggregation scratch (must run every replay)
// ---------------------------------------------------------------------------
__global__ void zero_agg_kernel() {
    int i = blockIdx.x * blockDim.x + threadIdx.x;
    ((float4*)g_agg)[i] = make_float4(0.f, 0.f, 0.f, 0.f);
}

// ---------------------------------------------------------------------------
// Edge kernel: mij = silu(silu([h[row],h[col]]@W1+b1)@W2+b2); agg[row] += mij
// 64 edges per block, 256 threads, 4x4 micro-tiles via packed FFMA2.
// ---------------------------------------------------------------------------
#define EDGE_SMEM ((64*128 + 128*64 + 64*68) * 4 + 2 * 64 * 4)

__global__ void __launch_bounds__(256, 2) edge_kernel(
    const float* __restrict__ h, const int* __restrict__ erow, const int* __restrict__ ecol,
    const float* __restrict__ W1, const float* __restrict__ b1,
    const float* __restrict__ W2, const float* __restrict__ b2,
    float* __restrict__ mij)
{
    extern __shared__ float sm[];
    float* Xs = sm;                     // 64 x 128
    float* Ws = Xs + 64 * 128;          // 128 x 64 (W1, then W2)
    float* Hs = Ws + 128 * 64;          // 64 x 68 (padded)
    int*   irs = (int*)(Hs + 64 * 68);  // 64 row ids
    int*   ics = irs + 64;              // 64 col ids

    const int tid = threadIdx.x;
    const int eb  = blockIdx.x * 64;

    if (tid < 64)       irs[tid]      = erow[eb + tid];
    else if (tid < 128) ics[tid - 64] = ecol[eb + tid - 64];
    __syncthreads();

    // gather X = [h[row] | h[col]] as float4 (coalesced over 64B chunks)
    const float4* h4 = (const float4*)h;
    float4* X4 = (float4*)Xs;
#pragma unroll
    for (int i = 0; i < 8; i++) {
        int f = i * 256 + tid;
        int r = f >> 5, p = f & 31;
        int node = (p < 16) ? irs[r] : ics[r];
        X4[f] = h4[node * 16 + (p & 15)];
    }
    // stage W1
    float4* Ws4 = (float4*)Ws;
    const float4* W14 = (const float4*)W1;
#pragma unroll
    for (int i = 0; i < 8; i++) Ws4[i * 256 + tid] = W14[i * 256 + tid];
    __syncthreads();

    const int tx = tid & 15, ty = tid >> 4;
    const int r0 = ty * 4, c0 = tx * 4;

    // acc[i][j2]: row r0+i, column pair (c0+2*j2, c0+2*j2+1)
    uint64_t acc[4][2];
#pragma unroll
    for (int i = 0; i < 4; i++) { acc[i][0] = 0ull; acc[i][1] = 0ull; }

    // layer 1: [64x128] @ [128x64]
#pragma unroll 4
    for (int k = 0; k < 128; k++) {
        float4 w = *(const float4*)&Ws[k * 64 + c0];
        uint64_t w01 = pk2(w.x, w.y);
        uint64_t w23 = pk2(w.z, w.w);
#pragma unroll
        for (int i = 0; i < 4; i++) {
            uint64_t xa = dupf(Xs[(r0 + i) * 128 + k]);
            fma2(acc[i][0], xa, w01);
            fma2(acc[i][1], xa, w23);
        }
    }
    {
        float4 bb = *(const float4*)&b1[c0];
#pragma unroll
        for (int i = 0; i < 4; i++) {
            float2 p0 = unpk(acc[i][0]), p1 = unpk(acc[i][1]);
            float4 v;
            v.x = silu_f(p0.x + bb.x);
            v.y = silu_f(p0.y + bb.y);
            v.z = silu_f(p1.x + bb.z);
            v.w = silu_f(p1.y + bb.w);
            *(float4*)&Hs[(r0 + i) * 68 + c0] = v;
        }
    }
    __syncthreads();
    // stage W2
    const float4* W24 = (const float4*)W2;
#pragma unroll
    for (int i = 0; i < 4; i++) Ws4[i * 256 + tid] = W24[i * 256 + tid];
    __syncthreads();

#pragma unroll
    for (int i = 0; i < 4; i++) { acc[i][0] = 0ull; acc[i][1] = 0ull; }

    // layer 2: [64x64] @ [64x64]
#pragma unroll 4
    for (int k = 0; k < 64; k++) {
        float4 w = *(const float4*)&Ws[k * 64 + c0];
        uint64_t w01 = pk2(w.x, w.y);
        uint64_t w23 = pk2(w.z, w.w);
#pragma unroll
        for (int i = 0; i < 4; i++) {
            uint64_t xa = dupf(Hs[(r0 + i) * 68 + k]);
            fma2(acc[i][0], xa, w01);
            fma2(acc[i][1], xa, w23);
        }
    }
    float4 b2v = *(const float4*)&b2[c0];
#pragma unroll
    for (int i = 0; i < 4; i++) {
        float2 p0 = unpk(acc[i][0]), p1 = unpk(acc[i][1]);
        float4 m;
        m.x = silu_f(p0.x + b2v.x);
        m.y = silu_f(p0.y + b2v.y);
        m.z = silu_f(p1.x + b2v.z);
        m.w = silu_f(p1.y + b2v.w);
        size_t ge = (size_t)(eb + r0 + i);
        *(float4*)&mij[ge * 64 + c0] = m;
        float* ap = &g_agg[(size_t)irs[r0 + i] * 64 + c0];
        asm volatile("red.global.add.v4.f32 [%0], {%1,%2,%3,%4};"
                     :: "l"(ap), "f"(m.x), "f"(m.y), "f"(m.z), "f"(m.w) : "memory");
    }
}

// ---------------------------------------------------------------------------
// 3-qubit statevector circuit (per node, per thread)
// ---------------------------------------------------------------------------
__device__ __forceinline__ void apply_rx3(float* ar, float* ai, float cb, float sb) {
#pragma unroll
    for (int q = 0; q < 3; q++) {
        int st = 4 >> q;
#pragma unroll
        for (int i = 0; i < 8; i++) {
            if (i & st) continue;
            int j = i + st;
            float a0r = ar[i], a0i = ai[i], a1r = ar[j], a1i = ai[j];
            ar[i] =  cb * a0r + sb * a1i;
            ai[i] =  cb * a0i - sb * a1r;
            ar[j] =  sb * a0i + cb * a1r;
            ai[j] = -sb * a0r + cb * a1i;
        }
    }
}

__device__ __forceinline__ void apply_rz(float* ar, float* ai, int st, float theta) {
    float s, c;
    sincosf(0.5f * theta, &s, &c);
#pragma unroll
    for (int i = 0; i < 8; i++) {
        float r = ar[i], im = ai[i];
        if (i & st) { ar[i] = r * c - im * s; ai[i] = im * c + r * s; }
        else        { ar[i] = r * c + im * s; ai[i] = im * c - r * s; }
    }
}

__device__ __forceinline__ void apply_h(float* ar, float* ai, int st) {
    const float SQ = 0.70710678118654752f;
#pragma unroll
    for (int i = 0; i < 8; i++) {
        if (i & st) continue;
        int j = i + st;
        float a0r = ar[i], a0i = ai[i], a1r = ar[j], a1i = ai[j];
        ar[i] = (a0r + a1r) * SQ; ai[i] = (a0i + a1i) * SQ;
        ar[j] = (a0r - a1r) * SQ; ai[j] = (a0i - a1i) * SQ;
    }
}

__device__ void qcircuit(const float* x, float alpha, float beta, float gamma, float delta,
                         const float* __restrict__ Lam, float* outq)
{
    float ar[8], ai[8];
#pragma unroll
    for (int i = 0; i < 8; i++) { ar[i] = 0.f; ai[i] = 0.f; }
    ar[0] = 1.f;

    // 1) data-encoding RY(alpha * x_q)
#pragma unroll
    for (int q = 0; q < 3; q++) {
        float s, c;
        sincosf(0.5f * alpha * x[q], &s, &c);
        int st = 4 >> q;
#pragma unroll
        for (int i = 0; i < 8; i++) {
            if (i & st) continue;
            int j = i + st;
            float a0r = ar[i], a0i = ai[i], a1r = ar[j], a1i = ai[j];
            ar[i] = c * a0r - s * a1r; ai[i] = c * a0i - s * a1i;
            ar[j] = s * a0r + c * a1r; ai[j] = s * a0i + c * a1i;
        }
    }
    // 2) IsingZZ coupling
#pragma unroll
    for (int qi = 0; qi < 3; qi++)
#pragma unroll
        for (int qj = qi + 1; qj < 3; qj++) {
            float phi = 0.5f * gamma * (Lam[qi * 3 + qj] + Lam[qj * 3 + qi]);
            float sp, cp;
            sincosf(0.5f * phi, &sp, &cp);
#pragma unroll
            for (int i = 0; i < 8; i++) {
                int bi = (i >> (2 - qi)) & 1, bj = (i >> (2 - qj)) & 1;
                float pi = (bi ^ bj) ? sp : -sp;
                float r = ar[i] * cp - ai[i] * pi;
                ai[i]   = ar[i] * pi + ai[i] * cp;
                ar[i]   = r;
            }
        }
    // 3) kinetic RX(beta)
    float sb, cb;
    sincosf(0.5f * beta, &sb, &cb);
    apply_rx3(ar, ai, cb, sb);
    // 4) anharmonic per qubit
#pragma unroll
    for (int q = 0; q < 3; q++) {
        int st = 4 >> q;
        float x2 = x[q] * x[q];
        apply_rz(ar, ai, st, delta * (1.f - 0.5f * x2));
        apply_h(ar, ai, st);
        apply_rz(ar, ai, st, delta * x2);
        apply_h(ar, ai, st);
    }
    // 5) final RX(beta)
    apply_rx3(ar, ai, cb, sb);

    float e0 = 0.f, e1 = 0.f, e2 = 0.f;
#pragma unroll
    for (int i = 0; i < 8; i++) {
        float p = ar[i] * ar[i] + ai[i] * ai[i];
        e0 += (i & 4) ? -p : p;
        e1 += (i & 2) ? -p : p;
        e2 += (i & 1) ? -p : p;
    }
    outq[0] = e0; outq[1] = e1; outq[2] = e2;
}

// ---------------------------------------------------------------------------
// Node kernel: a=[h,agg/100]; q_in = silu(a@qW1+qb1)@qW2+qb2; q_out = circuit;
// out = h + silu([a,q_out]@pW1+pb1)@pW2+pb2.  64 nodes per block.
// ---------------------------------------------------------------------------
#define NODE_SMEM ((64*132 + 131*64 + 64*68) * 4)

__global__ void __launch_bounds__(256, 2) node_kernel(
    const float* __restrict__ h,
    const float* __restrict__ qW1, const float* __restrict__ qb1,
    const float* __restrict__ qW2, const float* __restrict__ qb2,
    const float* __restrict__ pW1, const float* __restrict__ pb1,
    const float* __restrict__ pW2, const float* __restrict__ pb2,
    const float* __restrict__ alpha_p, const float* __restrict__ beta_p,
    const float* __restrict__ gamma_p, const float* __restrict__ delta_p,
    const float* __restrict__ Lam,
    float* __restrict__ out)
{
    extern __shared__ float sm[];
    float* Xs = sm;              // 64 x 132 : [h(64) | agg/100(64) | q_out(3) | pad]
    float* Ws = Xs + 64 * 132;   // up to 131 x 64
    float* Hs = Ws + 131 * 64;   // 64 x 68

    const int tid = threadIdx.x;
    const int nb  = blockIdx.x * 64;

    const float4* h4 = (const float4*)h;
    const float4* a4 = (const float4*)g_agg;
#pragma unroll
    for (int i = 0; i < 8; i++) {
        int f = i * 256 + tid;
        int r = f >> 5, p = f & 31;
        int node = nb + r;
        float4 v = make_float4(0.f, 0.f, 0.f, 0.f);
        if (node < NN) {
            if (p < 16) v = h4[node * 16 + p];
            else {
                v = a4[node * 16 + (p - 16)];
                v.x *= 0.01f; v.y *= 0.01f; v.z *= 0.01f; v.w *= 0.01f;
            }
        }
        ((float4*)Xs)[r * 33 + p] = v;
    }
    if (tid < 64) ((float4*)Xs)[tid * 33 + 32] = make_float4(0.f, 0.f, 0.f, 0.f);

    float4* Ws4 = (float4*)Ws;
#pragma unroll
    for (int i = 0; i < 8; i++) Ws4[i * 256 + tid] = ((const float4*)qW1)[i * 256 + tid];
    __syncthreads();

    const int tx = tid & 15, ty = tid >> 4;
    const int r0 = ty * 4, c0 = tx * 4;
    uint64_t acc[4][2];

    // phase A: H = silu(X[:, :128] @ qW1 + qb1)
#pragma unroll
    for (int i = 0; i < 4; i++) { acc[i][0] = 0ull; acc[i][1] = 0ull; }
#pragma unroll 4
    for (int k = 0; k < 128; k++) {
        float4 w = *(const float4*)&Ws[k * 64 + c0];
        uint64_t w01 = pk2(w.x, w.y);
        uint64_t w23 = pk2(w.z, w.w);
#pragma unroll
        for (int i = 0; i < 4; i++) {
            uint64_t xa = dupf(Xs[(r0 + i) * 132 + k]);
            fma2(acc[i][0], xa, w01);
            fma2(acc[i][1], xa, w23);
        }
    }
    {
        float4 bb = *(const float4*)&qb1[c0];
#pragma unroll
        for (int i = 0; i < 4; i++) {
            float2 p0 = unpk(acc[i][0]), p1 = unpk(acc[i][1]);
            float4 v;
            v.x = silu_f(p0.x + bb.x);
            v.y = silu_f(p0.y + bb.y);
            v.z = silu_f(p1.x + bb.z);
            v.w = silu_f(p1.y + bb.w);
            *(float4*)&Hs[(r0 + i) * 68 + c0] = v;
        }
    }
    __syncthreads();

    // phase B: q_in = H @ qW2 + qb2 ; quantum circuit (one thread per node)
    if (tid < 64) {
        float qin[3] = { qb2[0], qb2[1], qb2[2] };
        for (int k = 0; k < 64; k++) {
            float hv = Hs[tid * 68 + k];
            qin[0] += hv * qW2[k * 3 + 0];
            qin[1] += hv * qW2[k * 3 + 1];
            qin[2] += hv * qW2[k * 3 + 2];
        }
        float qo[3];
        qcircuit(qin, *alpha_p, *beta_p, *gamma_p, *delta_p, Lam, qo);
        Xs[tid * 132 + 128] = qo[0];
        Xs[tid * 132 + 129] = qo[1];
        Xs[tid * 132 + 130] = qo[2];
    }
    __syncthreads();

    // stage pW1 (131x64)
    for (int f = tid; f < 2096; f += 256) Ws4[f] = ((const float4*)pW1)[f];
    __syncthreads();

    // phase C: P = silu(X[:, :131] @ pW1 + pb1)
#pragma unroll
    for (int i = 0; i < 4; i++) { acc[i][0] = 0ull; acc[i][1] = 0ull; }
    for (int k = 0; k < 131; k++) {
        float4 w = *(const float4*)&Ws[k * 64 + c0];
        uint64_t w01 = pk2(w.x, w.y);
        uint64_t w23 = pk2(w.z, w.w);
#pragma unroll
        for (int i = 0; i < 4; i++) {
            uint64_t xa = dupf(Xs[(r0 + i) * 132 + k]);
            fma2(acc[i][0], xa, w01);
            fma2(acc[i][1], xa, w23);
        }
    }
    {
        float4 bb = *(const float4*)&pb1[c0];
#pragma unroll
        for (int i = 0; i < 4; i++) {
            float2 p0 = unpk(acc[i][0]), p1 = unpk(acc[i][1]);
            float4 v;
            v.x = silu_f(p0.x + bb.x);
            v.y = silu_f(p0.y + bb.y);
            v.z = silu_f(p1.x + bb.z);
            v.w = silu_f(p1.y + bb.w);
            *(float4*)&Hs[(r0 + i) * 68 + c0] = v;
        }
    }
    __syncthreads();

    // stage pW2 (64x64)
    for (int f = tid; f < 1024; f += 256) Ws4[f] = ((const float4*)pW2)[f];
    __syncthreads();

    // phase D: out = h + P @ pW2 + pb2
#pragma unroll
    for (int i = 0; i < 4; i++) { acc[i][0] = 0ull; acc[i][1] = 0ull; }
#pragma unroll 4
    for (int k = 0; k < 64; k++) {
        float4 w = *(const float4*)&Ws[k * 64 + c0];
        uint64_t w01 = pk2(w.x, w.y);
        uint64_t w23 = pk2(w.z, w.w);
#pragma unroll
        for (int i = 0; i < 4; i++) {
            uint64_t xa = dupf(Hs[(r0 + i) * 68 + k]);
            fma2(acc[i][0], xa, w01);
            fma2(acc[i][1], xa, w23);
        }
    }
    float4 bb = *(const float4*)&pb2[c0];
#pragma unroll
    for (int i = 0; i < 4; i++) {
        int node = nb + r0 + i;
        if (node < NN) {
            float2 p0 = unpk(acc[i][0]), p1 = unpk(acc[i][1]);
            float4 v;
            v.x = Xs[(r0 + i) * 132 + c0 + 0] + p0.x + bb.x;
            v.y = Xs[(r0 + i) * 132 + c0 + 1] + p0.y + bb.y;
            v.z = Xs[(r0 + i) * 132 + c0 + 2] + p1.x + bb.z;
            v.w = Xs[(r0 + i) * 132 + c0 + 3] + p1.y + bb.w;
            *(float4*)&out[(size_t)node * 64 + c0] = v;
        }
    }
}

// ---------------------------------------------------------------------------
extern "C" void kernel_launch(void* const* d_in, const int* in_sizes, int n_in,
                              void* d_out, int out_size) {
    const float* h   = (const float*)d_in[0];
    const int*   ei  = (const int*)d_in[1];
    const float* eW1 = (const float*)d_in[2];
    const float* eb1 = (const float*)d_in[3];
    const float* eW2 = (const float*)d_in[4];
    const float* eb2 = (const float*)d_in[5];
    const float* qW1 = (const float*)d_in[6];
    const float* qb1 = (const float*)d_in[7];
    const float* qW2 = (const float*)d_in[8];
    const float* qb2 = (const float*)d_in[9];
    const float* pW1 = (const float*)d_in[10];
    const float* pb1 = (const float*)d_in[11];
    const float* pW2 = (const float*)d_in[12];
    const float* pb2 = (const float*)d_in[13];
    const float* al  = (const float*)d_in[14];
    const float* be  = (const float*)d_in[15];
    const float* ga  = (const float*)d_in[16];
    const float* de  = (const float*)d_in[17];
    const float* Lam = (const float*)d_in[18];

    float* out = (float*)d_out;
    float* mij = out + (size_t)NN * DD;

    cudaFuncSetAttribute(edge_kernel, cudaFuncAttributeMaxDynamicSharedMemorySize, EDGE_SMEM);
    cudaFuncSetAttribute(node_kernel, cudaFuncAttributeMaxDynamicSharedMemorySize, NODE_SMEM);

    zero_agg_kernel<<<(NN * DD / 4) / 256, 256>>>();
    edge_kernel<<<NE / 64, 256, EDGE_SMEM>>>(h, ei, ei + NE, eW1, eb1, eW2, eb2, mij);
    node_kernel<<<(NN + 63) / 64, 256, NODE_SMEM>>>(h, qW1, qb1, qW2, qb2,
                                                    pW1, pb1, pW2, pb2,
                                                    al, be, ga, de, Lam, out);
}

// round 9
// speedup vs baseline: 1.2107x; 1.0014x over previous
#include <cuda_runtime.h>
#include <cstdint>

#define NN  50000
#define NE  800000
#define DD  64
#define HID 64

// Scratch: aggregation buffer (allocation-free rule -> __device__ global)
__device__ float g_agg[NN * DD];

__device__ __forceinline__ float silu_f(float v) {
    return v * (1.0f / (1.0f + __expf(-v)));
}

// ---------------- packed f32x2 helpers (Blackwell FFMA2) --------------------
__device__ __forceinline__ uint64_t dupf(float x) {
    uint64_t r; asm("mov.b64 %0, {%1, %1};" : "=l"(r) : "f"(x)); return r;
}
__device__ __forceinline__ uint64_t pk2(float lo, float hi) {
    uint64_t r; asm("mov.b64 %0, {%1, %2};" : "=l"(r) : "f"(lo), "f"(hi)); return r;
}
__device__ __forceinline__ void fma2(uint64_t& d, uint64_t a, uint64_t b) {
    asm("fma.rn.f32x2 %0, %1, %2, %0;" : "+l"(d) : "l"(a), "l"(b));
}
__device__ __forceinline__ float2 unpk(uint64_t v) {
    float2 f; asm("mov.b64 {%0, %1}, %2;" : "=f"(f.x), "=f"(f.y) : "l"(v)); return f;
}

// ---------------------------------------------------------------------------
// zero the aggregation scratch (must run every replay)
// ---------------------------------------------------------------------------
__global__ void zero_agg_kernel() {
    int i = blockIdx.x * blockDim.x + threadIdx.x;
    ((float4*)g_agg)[i] = make_float4(0.f, 0.f, 0.f, 0.f);
}

// ---------------------------------------------------------------------------
// Edge kernel: mij = silu(silu([h[row],h[col]]@W1+b1)@W2+b2); agg[row] += mij
// 64 edges per block, 256 threads, 4x4 micro-tiles via packed FFMA2.
// ---------------------------------------------------------------------------
#define EDGE_SMEM ((64*128 + 128*64 + 64*68) * 4 + 2 * 64 * 4)

__global__ void __launch_bounds__(256, 2) edge_kernel(
    const float* __restrict__ h, const int* __restrict__ erow, const int* __restrict__ ecol,
    const float* __restrict__ W1, const float* __restrict__ b1,
    const float* __restrict__ W2, const float* __restrict__ b2,
    float* __restrict__ mij)
{
    extern __shared__ float sm[];
    float* Xs = sm;                     // 64 x 128
    float* Ws = Xs + 64 * 128;          // 128 x 64 (W1, then W2)
    float* Hs = Ws + 128 * 64;          // 64 x 68 (padded)
    int*   irs = (int*)(Hs + 64 * 68);  // 64 row ids
    int*   ics = irs + 64;              // 64 col ids

    const int tid = threadIdx.x;
    const int eb  = blockIdx.x * 64;

    if (tid < 64)       irs[tid]      = erow[eb + tid];
    else if (tid < 128) ics[tid - 64] = ecol[eb + tid - 64];
    __syncthreads();

    // gather X = [h[row] | h[col]] as float4 (coalesced over 64B chunks)
    const float4* h4 = (const float4*)h;
    float4* X4 = (float4*)Xs;
#pragma unroll
    for (int i = 0; i < 8; i++) {
        int f = i * 256 + tid;
        int r = f >> 5, p = f & 31;
        int node = (p < 16) ? irs[r] : ics[r];
        X4[f] = h4[node * 16 + (p & 15)];
    }
    // stage W1
    float4* Ws4 = (float4*)Ws;
    const float4* W14 = (const float4*)W1;
#pragma unroll
    for (int i = 0; i < 8; i++) Ws4[i * 256 + tid] = W14[i * 256 + tid];
    __syncthreads();

    const int tx = tid & 15, ty = tid >> 4;
    const int r0 = ty * 4, c0 = tx * 4;

    // acc[i][j2]: row r0+i, column pair (c0+2*j2, c0+2*j2+1)
    uint64_t acc[4][2];
#pragma unroll
    for (int i = 0; i < 4; i++) { acc[i][0] = 0ull; acc[i][1] = 0ull; }

    // layer 1: [64x128] @ [128x64]
#pragma unroll 4
    for (int k = 0; k < 128; k++) {
        float4 w = *(const float4*)&Ws[k * 64 + c0];
        uint64_t w01 = pk2(w.x, w.y);
        uint64_t w23 = pk2(w.z, w.w);
#pragma unroll
        for (int i = 0; i < 4; i++) {
            uint64_t xa = dupf(Xs[(r0 + i) * 128 + k]);
            fma2(acc[i][0], xa, w01);
            fma2(acc[i][1], xa, w23);
        }
    }
    {
        float4 bb = *(const float4*)&b1[c0];
#pragma unroll
        for (int i = 0; i < 4; i++) {
            float2 p0 = unpk(acc[i][0]), p1 = unpk(acc[i][1]);
            float4 v;
            v.x = silu_f(p0.x + bb.x);
            v.y = silu_f(p0.y + bb.y);
            v.z = silu_f(p1.x + bb.z);
            v.w = silu_f(p1.y + bb.w);
            *(float4*)&Hs[(r0 + i) * 68 + c0] = v;
        }
    }
    __syncthreads();
    // stage W2
    const float4* W24 = (const float4*)W2;
#pragma unroll
    for (int i = 0; i < 4; i++) Ws4[i * 256 + tid] = W24[i * 256 + tid];
    __syncthreads();

#pragma unroll
    for (int i = 0; i < 4; i++) { acc[i][0] = 0ull; acc[i][1] = 0ull; }

    // layer 2: [64x64] @ [64x64]
#pragma unroll 4
    for (int k = 0; k < 64; k++) {
        float4 w = *(const float4*)&Ws[k * 64 + c0];
        uint64_t w01 = pk2(w.x, w.y);
        uint64_t w23 = pk2(w.z, w.w);
#pragma unroll
        for (int i = 0; i < 4; i++) {
            uint64_t xa = dupf(Hs[(r0 + i) * 68 + k]);
            fma2(acc[i][0], xa, w01);
            fma2(acc[i][1], xa, w23);
        }
    }
    float4 b2v = *(const float4*)&b2[c0];
#pragma unroll
    for (int i = 0; i < 4; i++) {
        float2 p0 = unpk(acc[i][0]), p1 = unpk(acc[i][1]);
        float4 m;
        m.x = silu_f(p0.x + b2v.x);
        m.y = silu_f(p0.y + b2v.y);
        m.z = silu_f(p1.x + b2v.z);
        m.w = silu_f(p1.y + b2v.w);
        size_t ge = (size_t)(eb + r0 + i);
        *(float4*)&mij[ge * 64 + c0] = m;
        float* ap = &g_agg[(size_t)irs[r0 + i] * 64 + c0];
        asm volatile("red.global.add.v4.f32 [%0], {%1,%2,%3,%4};"
                     :: "l"(ap), "f"(m.x), "f"(m.y), "f"(m.z), "f"(m.w) : "memory");
    }
}

// ---------------------------------------------------------------------------
// 3-qubit statevector circuit (per node, per thread)
// ---------------------------------------------------------------------------
__device__ __forceinline__ void apply_rx3(float* ar, float* ai, float cb, float sb) {
#pragma unroll
    for (int q = 0; q < 3; q++) {
        int st = 4 >> q;
#pragma unroll
        for (int i = 0; i < 8; i++) {
            if (i & st) continue;
            int j = i + st;
            float a0r = ar[i], a0i = ai[i], a1r = ar[j], a1i = ai[j];
            ar[i] =  cb * a0r + sb * a1i;
            ai[i] =  cb * a0i - sb * a1r;
            ar[j] =  sb * a0i + cb * a1r;
            ai[j] = -sb * a0r + cb * a1i;
        }
    }
}

__device__ __forceinline__ void apply_rz(float* ar, float* ai, int st, float theta) {
    float s, c;
    sincosf(0.5f * theta, &s, &c);
#pragma unroll
    for (int i = 0; i < 8; i++) {
        float r = ar[i], im = ai[i];
        if (i & st) { ar[i] = r * c - im * s; ai[i] = im * c + r * s; }
        else        { ar[i] = r * c + im * s; ai[i] = im * c - r * s; }
    }
}

__device__ __forceinline__ void apply_h(float* ar, float* ai, int st) {
    const float SQ = 0.70710678118654752f;
#pragma unroll
    for (int i = 0; i < 8; i++) {
        if (i & st) continue;
        int j = i + st;
        float a0r = ar[i], a0i = ai[i], a1r = ar[j], a1i = ai[j];
        ar[i] = (a0r + a1r) * SQ; ai[i] = (a0i + a1i) * SQ;
        ar[j] = (a0r - a1r) * SQ; ai[j] = (a0i - a1i) * SQ;
    }
}

__device__ void qcircuit(const float* x, float alpha, float beta, float gamma, float delta,
                         const float* __restrict__ Lam, float* outq)
{
    float ar[8], ai[8];
#pragma unroll
    for (int i = 0; i < 8; i++) { ar[i] = 0.f; ai[i] = 0.f; }
    ar[0] = 1.f;

    // 1) data-encoding RY(alpha * x_q)
#pragma unroll
    for (int q = 0; q < 3; q++) {
        float s, c;
        sincosf(0.5f * alpha * x[q], &s, &c);
        int st = 4 >> q;
#pragma unroll
        for (int i = 0; i < 8; i++) {
            if (i & st) continue;
            int j = i + st;
            float a0r = ar[i], a0i = ai[i], a1r = ar[j], a1i = ai[j];
            ar[i] = c * a0r - s * a1r; ai[i] = c * a0i - s * a1i;
            ar[j] = s * a0r + c * a1r; ai[j] = s * a0i + c * a1i;
        }
    }
    // 2) IsingZZ coupling
#pragma unroll
    for (int qi = 0; qi < 3; qi++)
#pragma unroll
        for (int qj = qi + 1; qj < 3; qj++) {
            float phi = 0.5f * gamma * (Lam[qi * 3 + qj] + Lam[qj * 3 + qi]);
            float sp, cp;
            sincosf(0.5f * phi, &sp, &cp);
#pragma unroll
            for (int i = 0; i < 8; i++) {
                int bi = (i >> (2 - qi)) & 1, bj = (i >> (2 - qj)) & 1;
                float pi = (bi ^ bj) ? sp : -sp;
                float r = ar[i] * cp - ai[i] * pi;
                ai[i]   = ar[i] * pi + ai[i] * cp;
                ar[i]   = r;
            }
        }
    // 3) kinetic RX(beta)
    float sb, cb;
    sincosf(0.5f * beta, &sb, &cb);
    apply_rx3(ar, ai, cb, sb);
    // 4) anharmonic per qubit
#pragma unroll
    for (int q = 0; q < 3; q++) {
        int st = 4 >> q;
        float x2 = x[q] * x[q];
        apply_rz(ar, ai, st, delta * (1.f - 0.5f * x2));
        apply_h(ar, ai, st);
        apply_rz(ar, ai, st, delta * x2);
        apply_h(ar, ai, st);
    }
    // 5) final RX(beta)
    apply_rx3(ar, ai, cb, sb);

    float e0 = 0.f, e1 = 0.f, e2 = 0.f;
#pragma unroll
    for (int i = 0; i < 8; i++) {
        float p = ar[i] * ar[i] + ai[i] * ai[i];
        e0 += (i & 4) ? -p : p;
        e1 += (i & 2) ? -p : p;
        e2 += (i & 1) ? -p : p;
    }
    outq[0] = e0; outq[1] = e1; outq[2] = e2;
}

// ---------------------------------------------------------------------------
// Node kernel: a=[h,agg/100]; q_in = silu(a@qW1+qb1)@qW2+qb2; q_out = circuit;
// out = h + silu([a,q_out]@pW1+pb1)@pW2+pb2.  64 nodes per block.
// ---------------------------------------------------------------------------
#define NODE_SMEM ((64*132 + 131*64 + 64*68) * 4)

__global__ void __launch_bounds__(256, 2) node_kernel(
    const float* __restrict__ h,
    const float* __restrict__ qW1, const float* __restrict__ qb1,
    const float* __restrict__ qW2, const float* __restrict__ qb2,
    const float* __restrict__ pW1, const float* __restrict__ pb1,
    const float* __restrict__ pW2, const float* __restrict__ pb2,
    const float* __restrict__ alpha_p, const float* __restrict__ beta_p,
    const float* __restrict__ gamma_p, const float* __restrict__ delta_p,
    const float* __restrict__ Lam,
    float* __restrict__ out)
{
    extern __shared__ float sm[];
    float* Xs = sm;              // 64 x 132 : [h(64) | agg/100(64) | q_out(3) | pad]
    float* Ws = Xs + 64 * 132;   // up to 131 x 64
    float* Hs = Ws + 131 * 64;   // 64 x 68

    const int tid = threadIdx.x;
    const int nb  = blockIdx.x * 64;

    const float4* h4 = (const float4*)h;
    const float4* a4 = (const float4*)g_agg;
#pragma unroll
    for (int i = 0; i < 8; i++) {
        int f = i * 256 + tid;
        int r = f >> 5, p = f & 31;
        int node = nb + r;
        float4 v = make_float4(0.f, 0.f, 0.f, 0.f);
        if (node < NN) {
            if (p < 16) v = h4[node * 16 + p];
            else {
                v = a4[node * 16 + (p - 16)];
                v.x *= 0.01f; v.y *= 0.01f; v.z *= 0.01f; v.w *= 0.01f;
            }
        }
        ((float4*)Xs)[r * 33 + p] = v;
    }
    if (tid < 64) ((float4*)Xs)[tid * 33 + 32] = make_float4(0.f, 0.f, 0.f, 0.f);

    float4* Ws4 = (float4*)Ws;
#pragma unroll
    for (int i = 0; i < 8; i++) Ws4[i * 256 + tid] = ((const float4*)qW1)[i * 256 + tid];
    __syncthreads();

    const int tx = tid & 15, ty = tid >> 4;
    const int r0 = ty * 4, c0 = tx * 4;
    uint64_t acc[4][2];

    // phase A: H = silu(X[:, :128] @ qW1 + qb1)
#pragma unroll
    for (int i = 0; i < 4; i++) { acc[i][0] = 0ull; acc[i][1] = 0ull; }
#pragma unroll 4
    for (int k = 0; k < 128; k++) {
        float4 w = *(const float4*)&Ws[k * 64 + c0];
        uint64_t w01 = pk2(w.x, w.y);
        uint64_t w23 = pk2(w.z, w.w);
#pragma unroll
        for (int i = 0; i < 4; i++) {
            uint64_t xa = dupf(Xs[(r0 + i) * 132 + k]);
            fma2(acc[i][0], xa, w01);
            fma2(acc[i][1], xa, w23);
        }
    }
    {
        float4 bb = *(const float4*)&qb1[c0];
#pragma unroll
        for (int i = 0; i < 4; i++) {
            float2 p0 = unpk(acc[i][0]), p1 = unpk(acc[i][1]);
            float4 v;
            v.x = silu_f(p0.x + bb.x);
            v.y = silu_f(p0.y + bb.y);
            v.z = silu_f(p1.x + bb.z);
            v.w = silu_f(p1.y + bb.w);
            *(float4*)&Hs[(r0 + i) * 68 + c0] = v;
        }
    }
    __syncthreads();

    // phase B: q_in = H @ qW2 + qb2 ; quantum circuit (one thread per node)
    if (tid < 64) {
        float qin[3] = { qb2[0], qb2[1], qb2[2] };
        for (int k = 0; k < 64; k++) {
            float hv = Hs[tid * 68 + k];
            qin[0] += hv * qW2[k * 3 + 0];
            qin[1] += hv * qW2[k * 3 + 1];
            qin[2] += hv * qW2[k * 3 + 2];
        }
        float qo[3];
        qcircuit(qin, *alpha_p, *beta_p, *gamma_p, *delta_p, Lam, qo);
        Xs[tid * 132 + 128] = qo[0];
        Xs[tid * 132 + 129] = qo[1];
        Xs[tid * 132 + 130] = qo[2];
    }
    __syncthreads();

    // stage pW1 (131x64)
    for (int f = tid; f < 2096; f += 256) Ws4[f] = ((const float4*)pW1)[f];
    __syncthreads();

    // phase C: P = silu(X[:, :131] @ pW1 + pb1)
#pragma unroll
    for (int i = 0; i < 4; i++) { acc[i][0] = 0ull; acc[i][1] = 0ull; }
    for (int k = 0; k < 131; k++) {
        float4 w = *(const float4*)&Ws[k * 64 + c0];
        uint64_t w01 = pk2(w.x, w.y);
        uint64_t w23 = pk2(w.z, w.w);
#pragma unroll
        for (int i = 0; i < 4; i++) {
            uint64_t xa = dupf(Xs[(r0 + i) * 132 + k]);
            fma2(acc[i][0], xa, w01);
            fma2(acc[i][1], xa, w23);
        }
    }
    {
        float4 bb = *(const float4*)&pb1[c0];
#pragma unroll
        for (int i = 0; i < 4; i++) {
            float2 p0 = unpk(acc[i][0]), p1 = unpk(acc[i][1]);
            float4 v;
            v.x = silu_f(p0.x + bb.x);
            v.y = silu_f(p0.y + bb.y);
            v.z = silu_f(p1.x + bb.z);
            v.w = silu_f(p1.y + bb.w);
            *(float4*)&Hs[(r0 + i) * 68 + c0] = v;
        }
    }
    __syncthreads();

    // stage pW2 (64x64)
    for (int f = tid; f < 1024; f += 256) Ws4[f] = ((const float4*)pW2)[f];
    __syncthreads();

    // phase D: out = h + P @ pW2 + pb2
#pragma unroll
    for (int i = 0; i < 4; i++) { acc[i][0] = 0ull; acc[i][1] = 0ull; }
#pragma unroll 4
    for (int k = 0; k < 64; k++) {
        float4 w = *(const float4*)&Ws[k * 64 + c0];
        uint64_t w01 = pk2(w.x, w.y);
        uint64_t w23 = pk2(w.z, w.w);
#pragma unroll
        for (int i = 0; i < 4; i++) {
            uint64_t xa = dupf(Hs[(r0 + i) * 68 + k]);
            fma2(acc[i][0], xa, w01);
            fma2(acc[i][1], xa, w23);
        }
    }
    float4 bb = *(const float4*)&pb2[c0];
#pragma unroll
    for (int i = 0; i < 4; i++) {
        int node = nb + r0 + i;
        if (node < NN) {
            float2 p0 = unpk(acc[i][0]), p1 = unpk(acc[i][1]);
            float4 v;
            v.x = Xs[(r0 + i) * 132 + c0 + 0] + p0.x + bb.x;
            v.y = Xs[(r0 + i) * 132 + c0 + 1] + p0.y + bb.y;
            v.z = Xs[(r0 + i) * 132 + c0 + 2] + p1.x + bb.z;
            v.w = Xs[(r0 + i) * 132 + c0 + 3] + p1.y + bb.w;
            *(float4*)&out[(size_t)node * 64 + c0] = v;
        }
    }
}

// ---------------------------------------------------------------------------
extern "C" void kernel_launch(void* const* d_in, const int* in_sizes, int n_in,
                              void* d_out, int out_size) {
    const float* h   = (const float*)d_in[0];
    const int*   ei  = (const int*)d_in[1];
    const float* eW1 = (const float*)d_in[2];
    const float* eb1 = (const float*)d_in[3];
    const float* eW2 = (const float*)d_in[4];
    const float* eb2 = (const float*)d_in[5];
    const float* qW1 = (const float*)d_in[6];
    const float* qb1 = (const float*)d_in[7];
    const float* qW2 = (const float*)d_in[8];
    const float* qb2 = (const float*)d_in[9];
    const float* pW1 = (const float*)d_in[10];
    const float* pb1 = (const float*)d_in[11];
    const float* pW2 = (const float*)d_in[12];
    const float* pb2 = (const float*)d_in[13];
    const float* al  = (const float*)d_in[14];
    const float* be  = (const float*)d_in[15];
    const float* ga  = (const float*)d_in[16];
    const float* de  = (const float*)d_in[17];
    const float* Lam = (const float*)d_in[18];

    float* out = (float*)d_out;
    float* mij = out + (size_t)NN * DD;

    cudaFuncSetAttribute(edge_kernel, cudaFuncAttributeMaxDynamicSharedMemorySize, EDGE_SMEM);
    cudaFuncSetAttribute(node_kernel, cudaFuncAttributeMaxDynamicSharedMemorySize, NODE_SMEM);

    zero_agg_kernel<<<(NN * DD / 4) / 256, 256>>>();
    edge_kernel<<<NE / 64, 256, EDGE_SMEM>>>(h, ei, ei + NE, eW1, eb1, eW2, eb2, mij);
    node_kernel<<<(NN + 63) / 64, 256, NODE_SMEM>>>(h, qW1, qb1, qW2, qb2,
                                                    pW1, pb1, pW2, pb2,
                                                    al, be, ga, de, Lam, out);
}